// round 14
// baseline (speedup 1.0000x reference)
#include <cuda_runtime.h>
#include <math.h>

// Problem constants: B=4, C=8, H=W=512
// pad = (int(sqrt(2)*512)-512)//2 + 1 = 107 ; padded = 726
#define BB 4
#define CC 8
#define HH 512
#define WW 512
#define PADC 107
#define PLANE (HH * WW)
#define DEG2RAD 0.017453292519943295f

// Block tile 64x4 (256 px, 1 px/thread); warp footprint 16x2.
// X-tap pairs fetched via one aligned float4 (+ rare predicated scalar).
__global__ __launch_bounds__(256)
void diff_pair_rotate_v4(const float* __restrict__ xin,
                         const float* __restrict__ yin,
                         const float* __restrict__ angles,
                         float* __restrict__ out)
{
    const int b    = blockIdx.y;
    const int tile = blockIdx.x;              // 0..1023 -> 8x128 tiles of 64x4
    const int tx   = (tile & 7) << 6;
    const int ty   = (tile >> 3) << 2;

    const int lane = threadIdx.x & 31;
    const int warp = threadIdx.x >> 5;        // 0..7
    const int px   = tx + ((warp & 3) << 4) + (lane & 15);
    const int py   = ty + ((warp >> 2) << 1) + (lane >> 4);

    const float rad = angles[b] * DEG2RAD;
    float sn, cs;
    sincosf(rad, &sn, &cs);

    // Collapsed affine source map (validated: rel_err 6.5e-5)
    const float step = 2.0f / 725.0f;
    const float d    = (float)PADC * step - 1.0f;
    const float K    = 363.0f * step;
    const float Ax   =  K * cs;
    const float Bx   = -K * sn;
    const float Cx   = 363.0f * d * (cs - sn) + 255.5f;
    const float Ay   =  K * sn;
    const float By   =  K * cs;
    const float Cy   = 363.0f * d * (sn + cs) + 255.5f;

    const float fx = fmaf((float)py, Bx, fmaf((float)px, Ax, Cx));
    const float fy = fmaf((float)py, By, fmaf((float)px, Ay, Cy));

    const float x0f = floorf(fx);
    const float y0f = floorf(fy);
    const float wx1 = fx - x0f, wx0 = 1.0f - wx1;
    const float wy1 = fy - y0f, wy0 = 1.0f - wy1;

    const int xs0 = (int)x0f;
    const int ys0 = (int)y0f;

    const bool vx0 = ((unsigned)xs0)       < (unsigned)WW;
    const bool vx1 = ((unsigned)(xs0 + 1)) < (unsigned)WW;
    const bool vy0 = ((unsigned)ys0)       < (unsigned)HH;
    const bool vy1 = ((unsigned)(ys0 + 1)) < (unsigned)HH;

    // Masked weights (zero-padding semantics; clamped reads are don't-cares)
    const float w00 = (vx0 & vy0) ? wx0 * wy0 : 0.0f;
    const float w10 = (vx1 & vy0) ? wx1 * wy0 : 0.0f;
    const float w01 = (vx0 & vy1) ? wx0 * wy1 : 0.0f;
    const float w11 = (vx1 & vy1) ? wx1 * wy1 : 0.0f;

    // Clamped, aligned tap addressing
    const int bx   = min(max(xs0, -1), 512);
    const int base = min(max(bx & ~3, 0), 508);
    const int s    = bx - base;               // in [-1, 4]
    const int r0   = min(max(ys0,     0), 511);
    const int r1   = min(max(ys0 + 1, 0), 511);

    const int i0  = r0 * WW + base;
    const int i1  = r1 * WW + base;
    const int ieo = min(base + 4, 508);       // straddle element (clamped)
    const int ie0 = r0 * WW + ieo;
    const int ie1 = r1 * WW + ieo;

    // Hoisted selection predicates (channel-invariant)
    const bool s0 = (s == 0);
    const bool s1 = (s == 1);
    const bool s2 = (s == 2);
    const bool s3 = (s >= 3);

    const int oi = py * WW + px;
    const float* __restrict__ xb = xin + (size_t)(b * CC) * PLANE;
    const float* __restrict__ yb = yin + (size_t)(b * CC) * PLANE;
    float* __restrict__ outx = out + (size_t)(b * CC) * PLANE + oi;
    float* __restrict__ outy = out + (size_t)(BB * CC) * PLANE
                                   + (size_t)(b * CC) * PLANE + oi;

    #pragma unroll 1
    for (int c = 0; c < CC; ++c) {
        const float* __restrict__ xp = xb + c * PLANE;
        const float* __restrict__ yp = yb + c * PLANE;

        const float4 qx0 = __ldg((const float4*)(xp + i0));
        const float4 qx1 = __ldg((const float4*)(xp + i1));
        const float4 qy0 = __ldg((const float4*)(yp + i0));
        const float4 qy1 = __ldg((const float4*)(yp + i1));

        float ex0 = 0.0f, ex1 = 0.0f, ey0 = 0.0f, ey1 = 0.0f;
        if (s3) {                              // ~25% of lanes
            ex0 = __ldg(xp + ie0);
            ex1 = __ldg(xp + ie1);
            ey0 = __ldg(yp + ie0);
            ey1 = __ldg(yp + ie1);
        }

        // t0 = element s of q ; t1 = element s+1 (e for s==3; q.x for s==-1)
        #define T0(q)      ( s3 ? (q).w : ( s2 ? (q).z : ( s1 ? (q).y : (q).x )))
        #define T1(q, e)   ( s3 ? (e)   : ( s2 ? (q).w : ( s1 ? (q).z : ( s0 ? (q).y : (q).x ))))

        float ax =       T0(qx0)      * w00;
        ax = fmaf(T1(qx0, ex0), w10, ax);
        ax = fmaf(T0(qx1),      w01, ax);
        ax = fmaf(T1(qx1, ex1), w11, ax);

        float ay =       T0(qy0)      * w00;
        ay = fmaf(T1(qy0, ey0), w10, ay);
        ay = fmaf(T0(qy1),      w01, ay);
        ay = fmaf(T1(qy1, ey1), w11, ay);

        #undef T0
        #undef T1

        outx[c * PLANE] = ax;
        outy[c * PLANE] = ay;
    }
}

extern "C" void kernel_launch(void* const* d_in, const int* in_sizes, int n_in,
                              void* d_out, int out_size)
{
    const float* x      = (const float*)d_in[0];
    const float* y      = (const float*)d_in[1];
    const float* angles = (const float*)d_in[2];
    float* out          = (float*)d_out;

    dim3 block(256);
    dim3 grid(1024, BB);    // 8x128 tiles of 64x4, 4 batches
    diff_pair_rotate_v4<<<grid, block>>>(x, y, angles, out);
}

// round 16
// speedup vs baseline: 1.2059x; 1.2059x over previous
#include <cuda_runtime.h>
#include <math.h>

// Problem constants: B=4, C=8, H=W=512
// pad = (int(sqrt(2)*512)-512)//2 + 1 = 107 ; padded = 726
#define BB 4
#define CC 8
#define HH 512
#define WW 512
#define PADC 107
#define PLANE (HH * WW)
#define DEG2RAD 0.017453292519943295f

// Block tile 64x4 (256 px, 1 px/thread); warp footprint 16x2.
// X-tap pairs via one aligned float2 (8B fetched = 8B used) + predicated
// scalar straddle for odd-offset lanes (~50%).
__global__ __launch_bounds__(256)
void diff_pair_rotate_v2(const float* __restrict__ xin,
                         const float* __restrict__ yin,
                         const float* __restrict__ angles,
                         float* __restrict__ out)
{
    const int b    = blockIdx.y;
    const int tile = blockIdx.x;              // 0..1023 -> 8x128 tiles of 64x4
    const int tx   = (tile & 7) << 6;
    const int ty   = (tile >> 3) << 2;

    const int lane = threadIdx.x & 31;
    const int warp = threadIdx.x >> 5;        // 0..7
    const int px   = tx + ((warp & 3) << 4) + (lane & 15);
    const int py   = ty + ((warp >> 2) << 1) + (lane >> 4);

    const float rad = angles[b] * DEG2RAD;
    float sn, cs;
    sincosf(rad, &sn, &cs);

    // Collapsed affine source map (validated: rel_err 6.5e-5)
    const float step = 2.0f / 725.0f;
    const float d    = (float)PADC * step - 1.0f;
    const float K    = 363.0f * step;
    const float Ax   =  K * cs;
    const float Bx   = -K * sn;
    const float Cx   = 363.0f * d * (cs - sn) + 255.5f;
    const float Ay   =  K * sn;
    const float By   =  K * cs;
    const float Cy   = 363.0f * d * (sn + cs) + 255.5f;

    const float fx = fmaf((float)py, Bx, fmaf((float)px, Ax, Cx));
    const float fy = fmaf((float)py, By, fmaf((float)px, Ay, Cy));

    const float x0f = floorf(fx);
    const float y0f = floorf(fy);
    const float wx1 = fx - x0f, wx0 = 1.0f - wx1;
    const float wy1 = fy - y0f, wy0 = 1.0f - wy1;

    const int xs0 = (int)x0f;
    const int ys0 = (int)y0f;

    const bool vx0 = ((unsigned)xs0)       < (unsigned)WW;
    const bool vx1 = ((unsigned)(xs0 + 1)) < (unsigned)WW;
    const bool vy0 = ((unsigned)ys0)       < (unsigned)HH;
    const bool vy1 = ((unsigned)(ys0 + 1)) < (unsigned)HH;

    // Masked weights (zero-padding semantics; clamped reads are don't-cares)
    const float w00 = (vx0 & vy0) ? wx0 * wy0 : 0.0f;
    const float w10 = (vx1 & vy0) ? wx1 * wy0 : 0.0f;
    const float w01 = (vx0 & vy1) ? wx0 * wy1 : 0.0f;
    const float w11 = (vx1 & vy1) ? wx1 * wy1 : 0.0f;

    // Clamped, 8B-aligned tap addressing
    const int bx   = min(max(xs0, -1), 512);
    const int base = min(max(bx & ~1, 0), 510);   // even, in [0,510]
    const int s    = bx - base;                   // in {-1,0,1,2}
    const int r0   = min(max(ys0,     0), 511);
    const int r1   = min(max(ys0 + 1, 0), 511);

    const int i0  = r0 * WW + base;               // 8B-aligned
    const int i1  = r1 * WW + base;
    const int ieo = min(base + 2, 511);           // straddle element (clamped)
    const int ie0 = r0 * WW + ieo;
    const int ie1 = r1 * WW + ieo;

    // Hoisted selection predicates (channel-invariant)
    const bool p1  = (s == 1);                    // odd offset -> straddle
    const bool pm1 = (s == -1);                   // xs0 == -1 -> t1 = arr[0]

    const int oi = py * WW + px;
    const float* __restrict__ xb = xin + (size_t)(b * CC) * PLANE;
    const float* __restrict__ yb = yin + (size_t)(b * CC) * PLANE;
    float* __restrict__ outx = out + (size_t)(b * CC) * PLANE + oi;
    float* __restrict__ outy = out + (size_t)(BB * CC) * PLANE
                                   + (size_t)(b * CC) * PLANE + oi;

    #pragma unroll 4
    for (int c = 0; c < CC; ++c) {
        const float* __restrict__ xp = xb + c * PLANE;
        const float* __restrict__ yp = yb + c * PLANE;

        const float2 qx0 = __ldg((const float2*)(xp + i0));
        const float2 qx1 = __ldg((const float2*)(xp + i1));
        const float2 qy0 = __ldg((const float2*)(yp + i0));
        const float2 qy1 = __ldg((const float2*)(yp + i1));

        float ex0 = 0.0f, ex1 = 0.0f, ey0 = 0.0f, ey1 = 0.0f;
        if (p1) {                                 // ~50% of lanes
            ex0 = __ldg(xp + ie0);
            ex1 = __ldg(xp + ie1);
            ey0 = __ldg(yp + ie0);
            ey1 = __ldg(yp + ie1);
        }

        // t0 = element s ; t1 = element s+1 (e for s==1; q.x for s==-1)
        #define T0(q)      ( p1 ? (q).y : (q).x )
        #define T1(q, e)   ( pm1 ? (q).x : ( p1 ? (e) : (q).y ) )

        float ax =       T0(qx0)      * w00;
        ax = fmaf(T1(qx0, ex0), w10, ax);
        ax = fmaf(T0(qx1),      w01, ax);
        ax = fmaf(T1(qx1, ex1), w11, ax);

        float ay =       T0(qy0)      * w00;
        ay = fmaf(T1(qy0, ey0), w10, ay);
        ay = fmaf(T0(qy1),      w01, ay);
        ay = fmaf(T1(qy1, ey1), w11, ay);

        #undef T0
        #undef T1

        outx[c * PLANE] = ax;
        outy[c * PLANE] = ay;
    }
}

extern "C" void kernel_launch(void* const* d_in, const int* in_sizes, int n_in,
                              void* d_out, int out_size)
{
    const float* x      = (const float*)d_in[0];
    const float* y      = (const float*)d_in[1];
    const float* angles = (const float*)d_in[2];
    float* out          = (float*)d_out;

    dim3 block(256);
    dim3 grid(1024, BB);    // 8x128 tiles of 64x4, 4 batches
    diff_pair_rotate_v2<<<grid, block>>>(x, y, angles, out);
}